// round 8
// baseline (speedup 1.0000x reference)
#include <cuda_runtime.h>
#include <cuda_bf16.h>
#include <cstdint>
#include <math.h>

#define NB 25
#define BATCH 4096
#define DN 1024
#define RS (NB * DN)
#define NMAT (2 * NB)
#define MM ((size_t)DN * DN)
#define NSQ 10
#define BK 64
#define NKS (DN / BK)            // 16 k-stages
#define RSEB 144                 // smem row stride bytes (128B data + 16B pad)
#define MATB (128 * RSEB)        // 18432 B per matrix tile
#define STG4 (4 * MATB)          // 73728 B per stage (4 mats)
#define SMEM_BYTES (3 * STG4)    // 221184, 3-stage pipeline

typedef __nv_bfloat16 bf16;

// ----------------------------- scratch -------------------------------------
__device__ bf16  g_xhi[(size_t)BATCH * RS];
__device__ bf16  g_xlo[(size_t)BATCH * RS];
__device__ bf16  g_wth[NMAT * MM];
__device__ bf16  g_wtl[NMAT * MM];
__device__ float g_G  [NMAT * MM];
__device__ bf16  g_P0h[NMAT * MM];
__device__ bf16  g_P0l[NMAT * MM];
__device__ bf16  g_P1h[NMAT * MM];
__device__ bf16  g_P1l[NMAT * MM];
__device__ bf16  g_hhi[(size_t)BATCH * RS];
__device__ bf16  g_hlo[(size_t)BATCH * RS];
__device__ float g_tr [(NSQ + 1) * NMAT];
__device__ float g_v  [NMAT * DN];
__device__ float g_gv [NMAT * DN];
__device__ float g_is [NMAT];

// ----------------------------- PTX helpers ---------------------------------
__device__ __forceinline__ uint32_t smem_u32(const void* p) {
    uint32_t a;
    asm("{ .reg .u64 t; cvta.to.shared.u64 t, %1; cvt.u32.u64 %0, t; }" : "=r"(a) : "l"(p));
    return a;
}
__device__ __forceinline__ void cp16(uint32_t s, const void* g) {
    asm volatile("cp.async.cg.shared.global [%0], [%1], 16;" :: "r"(s), "l"(g));
}
#define CP_COMMIT() asm volatile("cp.async.commit_group;" ::: "memory")
#define CP_WAIT(N)  asm volatile("cp.async.wait_group %0;" :: "n"(N) : "memory")

#define LDSM4(r0, r1, r2, r3, addr) \
    asm volatile("ldmatrix.sync.aligned.m8n8.x4.shared.b16 {%0,%1,%2,%3}, [%4];" \
        : "=r"(r0), "=r"(r1), "=r"(r2), "=r"(r3) : "r"(addr))

#define MMA16816(c, a, b) \
    asm volatile("mma.sync.aligned.m16n8k16.row.col.f32.bf16.bf16.f32 " \
        "{%0,%1,%2,%3}, {%4,%5,%6,%7}, {%8,%9}, {%0,%1,%2,%3};" \
        : "+f"((c)[0]), "+f"((c)[1]), "+f"((c)[2]), "+f"((c)[3]) \
        : "r"((a)[0]), "r"((a)[1]), "r"((a)[2]), "r"((a)[3]), "r"((b)[0]), "r"((b)[1]))

// ----------------------------- conversions ---------------------------------
__global__ void __launch_bounds__(256) conv_split(const float* __restrict__ in,
                                                  bf16* __restrict__ hi, bf16* __restrict__ lo)
{
    size_t i = ((size_t)blockIdx.x * 256 + threadIdx.x) * 4;
    float4 v = *(const float4*)(in + i);
    bf16 h0 = __float2bfloat16(v.x), h1 = __float2bfloat16(v.y);
    bf16 h2 = __float2bfloat16(v.z), h3 = __float2bfloat16(v.w);
    hi[i+0] = h0; hi[i+1] = h1; hi[i+2] = h2; hi[i+3] = h3;
    lo[i+0] = __float2bfloat16(v.x - __bfloat162float(h0));
    lo[i+1] = __float2bfloat16(v.y - __bfloat162float(h1));
    lo[i+2] = __float2bfloat16(v.z - __bfloat162float(h2));
    lo[i+3] = __float2bfloat16(v.w - __bfloat162float(h3));
}

__global__ void __launch_bounds__(256) conv_wT(const float* __restrict__ w,
                                               bf16* __restrict__ hi, bf16* __restrict__ lo)
{
    const int m = blockIdx.z;
    const float* W = w + (size_t)m * MM;
    bf16* Hi = hi + (size_t)m * MM;
    bf16* Lo = lo + (size_t)m * MM;
    __shared__ float t[32][33];
    const int r0 = blockIdx.y * 32, c0 = blockIdx.x * 32;
    const int tr = threadIdx.x >> 5, tc = threadIdx.x & 31;
#pragma unroll
    for (int i = 0; i < 4; i++)
        t[tr + 8 * i][tc] = W[(size_t)(r0 + tr + 8 * i) * DN + c0 + tc];
    __syncthreads();
#pragma unroll
    for (int i = 0; i < 4; i++) {
        int rr = tr + 8 * i;
        float v = t[tc][rr];
        bf16 h = __float2bfloat16(v);
        size_t o = (size_t)(c0 + rr) * DN + r0 + tc;
        Hi[o] = h;
        Lo[o] = __float2bfloat16(v - __bfloat162float(h));
    }
}

// ------------------- 3-term hi/lo GEMM, 3-stage pipeline --------------------
// C[r][c] = scl * sum_k A[r][k] * B[c][k]   (both operands K-major)
// MODE 0: Gram   -> Cf (fp32) + Chi/Clo    [triangular grid + mirror]
// MODE 1: square -> Chi/Clo, scl=(1/tr)^2  [triangular grid + mirror]
// MODE 2: MLP1   -> Chi/Clo = gelu(C*is + b1)
// MODE 3: MLP2   -> Cf = C*is + b2
template <int MODE>
__global__ void __launch_bounds__(256, 1) gemm_k(
    const bf16* __restrict__ Ahi, const bf16* __restrict__ Alo, long lda, long aoffz,
    const bf16* __restrict__ Bhi, const bf16* __restrict__ Blo,
    float* __restrict__ Cf, bf16* __restrict__ Chi, bf16* __restrict__ Clo,
    long ldc, long coffz,
    const float* __restrict__ bias, const float* __restrict__ sc,
    const float* __restrict__ trin)
{
    extern __shared__ char smem[];
    const uint32_t sb = smem_u32(smem);

    const int tid = threadIdx.x;
    const int wid = tid >> 5, lane = tid & 31;
    const int wr = wid >> 1, wc = wid & 1;
    const int z = blockIdx.z;

    int row0, col0;
    if (MODE <= 1) {
        int t = blockIdx.x, ti = 0;
        while (t >= 8 - ti) { t -= 8 - ti; ti++; }
        row0 = ti * 128; col0 = (ti + t) * 128;
    } else {
        row0 = blockIdx.y * 128; col0 = blockIdx.x * 128;
    }

    const bf16* Ah = Ahi + (size_t)z * aoffz + (size_t)row0 * lda;
    const bf16* Al = Alo + (size_t)z * aoffz + (size_t)row0 * lda;
    const bf16* Bh = Bhi + (size_t)z * MM + (size_t)col0 * DN;
    const bf16* Bl = Blo + (size_t)z * MM + (size_t)col0 * DN;

    const bf16* gbase[4] = {Ah, Al, Bh, Bl};
    const long  gstr [4] = {lda, lda, DN, DN};

    // stage loader: 4 matrices x 128 rows x 64 bf16 (128B) each
    auto load_stage = [&](int st, int k0) {
        const uint32_t base = sb + (uint32_t)st * STG4;
        const int ch = tid & 7;
        const int rlo = tid >> 3;
#pragma unroll
        for (int t = 0; t < 16; t++) {
            const int mat = t >> 2;
            const int r = ((t & 3) << 5) + rlo;
            cp16(base + (uint32_t)mat * MATB + (uint32_t)(r * RSEB + ch * 16),
                 gbase[mat] + (long)r * gstr[mat] + k0 + ch * 8);
        }
        CP_COMMIT();
    };

    float acc[2][8][4];
#pragma unroll
    for (int mi = 0; mi < 2; mi++)
#pragma unroll
        for (int ni = 0; ni < 8; ni++)
#pragma unroll
            for (int q = 0; q < 4; q++) acc[mi][ni][q] = 0.0f;

    load_stage(0, 0);
    load_stage(1, BK);

    const int arow = (lane & 7) + ((lane >> 3) & 1) * 8;
    const int acol = (lane >> 4) * 16;
    const int brow = (lane & 7) + ((lane >> 4) & 1) * 8;
    const int bcol = ((lane >> 3) & 1) * 16;

    for (int s = 0; s < NKS; s++) {
        if (s < NKS - 1) { CP_WAIT(1); } else { CP_WAIT(0); }
        __syncthreads();
        if (s + 2 < NKS) load_stage((s + 2) % 3, (s + 2) * BK);

        const uint32_t stb = sb + (uint32_t)(s % 3) * STG4;
        const uint32_t aBh = stb + (uint32_t)((wr * 32 + arow) * RSEB) + acol;
        const uint32_t aBl = aBh + MATB;
        const uint32_t bBh = stb + 2u * MATB + (uint32_t)((wc * 64 + brow) * RSEB) + bcol;
        const uint32_t bBl = bBh + MATB;

#pragma unroll
        for (int kk = 0; kk < 4; kk++) {
            const uint32_t ko = (uint32_t)(kk * 32);
            uint32_t ah[2][4], al[2][4], bh[8][2], bl[8][2];
#pragma unroll
            for (int mi = 0; mi < 2; mi++) {
                LDSM4(ah[mi][0], ah[mi][1], ah[mi][2], ah[mi][3], aBh + ko + (uint32_t)(mi * 16 * RSEB));
                LDSM4(al[mi][0], al[mi][1], al[mi][2], al[mi][3], aBl + ko + (uint32_t)(mi * 16 * RSEB));
            }
#pragma unroll
            for (int p = 0; p < 4; p++) {
                LDSM4(bh[2*p][0], bh[2*p][1], bh[2*p+1][0], bh[2*p+1][1], bBh + ko + (uint32_t)(p * 16 * RSEB));
                LDSM4(bl[2*p][0], bl[2*p][1], bl[2*p+1][0], bl[2*p+1][1], bBl + ko + (uint32_t)(p * 16 * RSEB));
            }
#pragma unroll
            for (int mi = 0; mi < 2; mi++)
#pragma unroll
                for (int ni = 0; ni < 8; ni++) MMA16816(acc[mi][ni], ah[mi], bh[ni]);
#pragma unroll
            for (int mi = 0; mi < 2; mi++)
#pragma unroll
                for (int ni = 0; ni < 8; ni++) MMA16816(acc[mi][ni], ah[mi], bl[ni]);
#pragma unroll
            for (int mi = 0; mi < 2; mi++)
#pragma unroll
                for (int ni = 0; ni < 8; ni++) MMA16816(acc[mi][ni], al[mi], bh[ni]);
        }
        __syncthreads();
    }

    // ------------------------------ epilogue -------------------------------
    float scl = 1.0f;
    if (MODE == 1) { float it = 1.0f / trin[z]; scl = it * it; }
    if (MODE >= 2) scl = sc[z];
    const int gID = lane >> 2, tg = lane & 3;
    const bool mirror = (MODE <= 1) && (row0 != col0);
    float* ts = (float*)smem;

#pragma unroll
    for (int mi = 0; mi < 2; mi++)
#pragma unroll
        for (int ni = 0; ni < 8; ni++)
#pragma unroll
            for (int hf = 0; hf < 2; hf++) {
                const int rl = wr * 32 + mi * 16 + gID + hf * 8;
                const int cl = wc * 64 + ni * 8 + tg * 2;
                float v0 = acc[mi][ni][hf * 2 + 0] * scl;
                float v1 = acc[mi][ni][hf * 2 + 1] * scl;
                if (MODE >= 2) {
                    v0 += bias[z * DN + col0 + cl];
                    v1 += bias[z * DN + col0 + cl + 1];
                }
                if (MODE == 2) {
                    v0 = 0.5f * v0 * (1.0f + erff(v0 * 0.70710678118654752f));
                    v1 = 0.5f * v1 * (1.0f + erff(v1 * 0.70710678118654752f));
                }
                const size_t off = (size_t)z * coffz + (size_t)(row0 + rl) * ldc + col0 + cl;
                if (MODE == 0 || MODE == 3) {
                    float2 f2; f2.x = v0; f2.y = v1;
                    *(float2*)(Cf + off) = f2;
                }
                if (MODE <= 2) {
                    bf16 h0 = __float2bfloat16(v0);
                    bf16 h1 = __float2bfloat16(v1);
                    __nv_bfloat162 hh; hh.x = h0; hh.y = h1;
                    __nv_bfloat162 ll;
                    ll.x = __float2bfloat16(v0 - __bfloat162float(h0));
                    ll.y = __float2bfloat16(v1 - __bfloat162float(h1));
                    *(__nv_bfloat162*)(Chi + off) = hh;
                    *(__nv_bfloat162*)(Clo + off) = ll;
                }
                if (mirror) {
                    ts[rl * 129 + cl] = v0;
                    ts[rl * 129 + cl + 1] = v1;
                }
            }

    if (mirror) {
        __syncthreads();
#pragma unroll 4
        for (int i = 0; i < 32; i++) {
            int lin = i * 512 + tid * 2;
            int mr = lin >> 7, mc = lin & 127;
            float v0 = ts[mc * 129 + mr];
            float v1 = ts[(mc + 1) * 129 + mr];
            const size_t off = (size_t)z * coffz + (size_t)(col0 + mr) * ldc + row0 + mc;
            if (MODE == 0) {
                float2 f2; f2.x = v0; f2.y = v1;
                *(float2*)(Cf + off) = f2;
            }
            bf16 h0 = __float2bfloat16(v0);
            bf16 h1 = __float2bfloat16(v1);
            __nv_bfloat162 hh; hh.x = h0; hh.y = h1;
            __nv_bfloat162 ll;
            ll.x = __float2bfloat16(v0 - __bfloat162float(h0));
            ll.y = __float2bfloat16(v1 - __bfloat162float(h1));
            *(__nv_bfloat162*)(Chi + off) = hh;
            *(__nv_bfloat162*)(Clo + off) = ll;
        }
    }
}

// --------------------------- small kernels ----------------------------------
__global__ void __launch_bounds__(256) k_trace_f(const float* __restrict__ G,
                                                 float* __restrict__ out)
{
    const int m = blockIdx.x;
    float sum = 0.0f;
    for (int d = threadIdx.x; d < DN; d += 256)
        sum += G[(size_t)m * MM + (size_t)d * DN + d];
    __shared__ float red[256];
    red[threadIdx.x] = sum; __syncthreads();
    for (int off = 128; off > 0; off >>= 1) {
        if (threadIdx.x < off) red[threadIdx.x] += red[threadIdx.x + off];
        __syncthreads();
    }
    if (threadIdx.x == 0) out[m] = red[0];
}

__global__ void __launch_bounds__(256) k_trace_hl(const bf16* __restrict__ Ph,
                                                  const bf16* __restrict__ Pl,
                                                  float* __restrict__ out)
{
    const int m = blockIdx.x;
    float sum = 0.0f;
    for (int d = threadIdx.x; d < DN; d += 256) {
        size_t o = (size_t)m * MM + (size_t)d * DN + d;
        sum += __bfloat162float(Ph[o]) + __bfloat162float(Pl[o]);
    }
    __shared__ float red[256];
    red[threadIdx.x] = sum; __syncthreads();
    for (int off = 128; off > 0; off >>= 1) {
        if (threadIdx.x < off) red[threadIdx.x] += red[threadIdx.x + off];
        __syncthreads();
    }
    if (threadIdx.x == 0) out[m] = red[0];
}

__global__ void __launch_bounds__(256) k_rowsum(const bf16* __restrict__ Ph,
                                                const bf16* __restrict__ Pl,
                                                float* __restrict__ v)
{
    const int m = blockIdx.y, r = blockIdx.x;
    const size_t o = (size_t)m * MM + (size_t)r * DN;
    float sum = 0.0f;
    for (int c = threadIdx.x; c < DN; c += 256)
        sum += __bfloat162float(Ph[o + c]) + __bfloat162float(Pl[o + c]);
    __shared__ float red[256];
    red[threadIdx.x] = sum; __syncthreads();
    for (int off = 128; off > 0; off >>= 1) {
        if (threadIdx.x < off) red[threadIdx.x] += red[threadIdx.x + off];
        __syncthreads();
    }
    if (threadIdx.x == 0) v[m * DN + r] = red[0];
}

__global__ void __launch_bounds__(256) k_matvec(const float* __restrict__ G,
                                                const float* __restrict__ v,
                                                float* __restrict__ gv)
{
    const int m = blockIdx.y, r = blockIdx.x;
    const float* row = G + (size_t)m * MM + (size_t)r * DN;
    const float* vm = v + m * DN;
    float4 a = *(const float4*)&row[threadIdx.x * 4];
    float4 b = *(const float4*)&vm[threadIdx.x * 4];
    float sum = a.x * b.x + a.y * b.y + a.z * b.z + a.w * b.w;
    __shared__ float red[256];
    red[threadIdx.x] = sum; __syncthreads();
    for (int off = 128; off > 0; off >>= 1) {
        if (threadIdx.x < off) red[threadIdx.x] += red[threadIdx.x + off];
        __syncthreads();
    }
    if (threadIdx.x == 0) gv[m * DN + r] = red[0];
}

__global__ void __launch_bounds__(256) k_sigma(const float* __restrict__ v,
                                               const float* __restrict__ gv,
                                               float* __restrict__ is_)
{
    const int m = blockIdx.x;
    float num = 0.0f, den = 0.0f;
    for (int d = threadIdx.x; d < DN; d += 256) {
        float vv = v[m * DN + d];
        num += vv * gv[m * DN + d];
        den += vv * vv;
    }
    __shared__ float rn[256], rd[256];
    rn[threadIdx.x] = num; rd[threadIdx.x] = den; __syncthreads();
    for (int off = 128; off > 0; off >>= 1) {
        if (threadIdx.x < off) { rn[threadIdx.x] += rn[threadIdx.x + off]; rd[threadIdx.x] += rd[threadIdx.x + off]; }
        __syncthreads();
    }
    if (threadIdx.x == 0) is_[m] = sqrtf(rd[0] / rn[0]);
}

// ---------------------------------------------------------------------------
extern "C" void kernel_launch(void* const* d_in, const int* in_sizes, int n_in,
                              void* d_out, int out_size)
{
    const float* x  = (const float*)d_in[0];
    const float* w1 = (const float*)d_in[1];
    const float* b1 = (const float*)d_in[2];
    const float* w2 = (const float*)d_in[3];
    const float* b2 = (const float*)d_in[4];
    float* out = (float*)d_out;

    bf16 *xhi, *xlo, *wth, *wtl, *P0h, *P0l, *P1h, *P1l, *hhi, *hlo;
    float *G, *tr, *v, *gv, *is_;
    cudaGetSymbolAddress((void**)&xhi, g_xhi); cudaGetSymbolAddress((void**)&xlo, g_xlo);
    cudaGetSymbolAddress((void**)&wth, g_wth); cudaGetSymbolAddress((void**)&wtl, g_wtl);
    cudaGetSymbolAddress((void**)&G, g_G);
    cudaGetSymbolAddress((void**)&P0h, g_P0h); cudaGetSymbolAddress((void**)&P0l, g_P0l);
    cudaGetSymbolAddress((void**)&P1h, g_P1h); cudaGetSymbolAddress((void**)&P1l, g_P1l);
    cudaGetSymbolAddress((void**)&hhi, g_hhi); cudaGetSymbolAddress((void**)&hlo, g_hlo);
    cudaGetSymbolAddress((void**)&tr, g_tr);   cudaGetSymbolAddress((void**)&v, g_v);
    cudaGetSymbolAddress((void**)&gv, g_gv);   cudaGetSymbolAddress((void**)&is_, g_is);

    cudaFuncSetAttribute(gemm_k<0>, cudaFuncAttributeMaxDynamicSharedMemorySize, SMEM_BYTES);
    cudaFuncSetAttribute(gemm_k<1>, cudaFuncAttributeMaxDynamicSharedMemorySize, SMEM_BYTES);
    cudaFuncSetAttribute(gemm_k<2>, cudaFuncAttributeMaxDynamicSharedMemorySize, SMEM_BYTES);
    cudaFuncSetAttribute(gemm_k<3>, cudaFuncAttributeMaxDynamicSharedMemorySize, SMEM_BYTES);

    conv_split<<<(unsigned)((size_t)BATCH * RS / 4 / 256), 256>>>(x, xhi, xlo);
    conv_wT<<<dim3(32, 32, NB), 256>>>(w1, wth, wtl);
    conv_wT<<<dim3(32, 32, NB), 256>>>(w2, wth + (size_t)NB * MM, wtl + (size_t)NB * MM);

    // Gram: G (fp32) + P0 hi/lo, triangular grid; trace from fp32 G
    gemm_k<0><<<dim3(36, 1, NMAT), 256, SMEM_BYTES>>>(
        wth, wtl, DN, (long)MM, wth, wtl, G, P0h, P0l, DN, (long)MM,
        nullptr, nullptr, nullptr);
    k_trace_f<<<NMAT, 256>>>(G, tr);

    // hi/lo trace-normalized squarings (triangular + mirror)
    bf16 *pih = P0h, *pil = P0l, *poh = P1h, *pol = P1l;
    for (int s = 0; s < NSQ; s++) {
        gemm_k<1><<<dim3(36, 1, NMAT), 256, SMEM_BYTES>>>(
            pih, pil, DN, (long)MM, pih, pil, nullptr, poh, pol, DN, (long)MM,
            nullptr, nullptr, tr + s * NMAT);
        k_trace_hl<<<NMAT, 256>>>(poh, pol, tr + (s + 1) * NMAT);
        bf16* t1 = pih; pih = poh; poh = t1;
        bf16* t2 = pil; pil = pol; pol = t2;
    }

    // Rayleigh quotient on fp32 G with v = P_final @ 1
    k_rowsum<<<dim3(DN, NMAT), 256>>>(pih, pil, v);
    k_matvec<<<dim3(DN, NMAT), 256>>>(G, v, gv);
    k_sigma<<<NMAT, 256>>>(v, gv, is_);

    // MLP
    gemm_k<2><<<dim3(8, 32, NB), 256, SMEM_BYTES>>>(
        xhi, xlo, RS, (long)DN, wth, wtl, nullptr, hhi, hlo, RS, (long)DN,
        b1, is_, nullptr);
    gemm_k<3><<<dim3(8, 32, NB), 256, SMEM_BYTES>>>(
        hhi, hlo, RS, (long)DN, wth + (size_t)NB * MM, wtl + (size_t)NB * MM,
        out, nullptr, nullptr, RS, (long)DN, b2, is_ + NB, nullptr);
}

// round 10
// speedup vs baseline: 1.0049x; 1.0049x over previous
#include <cuda_runtime.h>
#include <cuda_bf16.h>
#include <cstdint>
#include <math.h>

#define NB 25
#define BATCH 4096
#define DN 1024
#define RS (NB * DN)
#define NMAT (2 * NB)
#define MM ((size_t)DN * DN)
#define NSQ 10                   // hi/lo squarings (ALL hi/lo — tail must stay precise)
#define BK 64
#define NKS (DN / BK)            // 16 k-stages
#define RSEB 144                 // smem row stride bytes (128B data + 16B pad)
#define MATB (128 * RSEB)        // 18432 B per matrix tile
#define STG4 (4 * MATB)          // 73728 B per stage (4 mats)
#define SMEM_BYTES (3 * STG4)    // 221184, 3-stage pipeline

typedef __nv_bfloat16 bf16;

// ----------------------------- scratch -------------------------------------
__device__ bf16  g_xhi[(size_t)BATCH * RS];
__device__ bf16  g_xlo[(size_t)BATCH * RS];
__device__ bf16  g_wth[NMAT * MM];
__device__ bf16  g_wtl[NMAT * MM];
__device__ float g_G  [NMAT * MM];
__device__ bf16  g_P0h[NMAT * MM];
__device__ bf16  g_P0l[NMAT * MM];
__device__ bf16  g_P1h[NMAT * MM];
__device__ bf16  g_P1l[NMAT * MM];
__device__ bf16  g_hhi[(size_t)BATCH * RS];
__device__ bf16  g_hlo[(size_t)BATCH * RS];
__device__ float g_tr [(NSQ + 1) * NMAT];
__device__ float g_v  [NMAT * DN];
__device__ float g_gv [NMAT * DN];
__device__ float g_is [NMAT];

// ----------------------------- PTX helpers ---------------------------------
__device__ __forceinline__ uint32_t smem_u32(const void* p) {
    uint32_t a;
    asm("{ .reg .u64 t; cvta.to.shared.u64 t, %1; cvt.u32.u64 %0, t; }" : "=r"(a) : "l"(p));
    return a;
}
__device__ __forceinline__ void cp16(uint32_t s, const void* g) {
    asm volatile("cp.async.cg.shared.global [%0], [%1], 16;" :: "r"(s), "l"(g));
}
#define CP_COMMIT() asm volatile("cp.async.commit_group;" ::: "memory")
#define CP_WAIT(N)  asm volatile("cp.async.wait_group %0;" :: "n"(N) : "memory")

#define LDSM4(r0, r1, r2, r3, addr) \
    asm volatile("ldmatrix.sync.aligned.m8n8.x4.shared.b16 {%0,%1,%2,%3}, [%4];" \
        : "=r"(r0), "=r"(r1), "=r"(r2), "=r"(r3) : "r"(addr))

#define MMA16816(c, a, b) \
    asm volatile("mma.sync.aligned.m16n8k16.row.col.f32.bf16.bf16.f32 " \
        "{%0,%1,%2,%3}, {%4,%5,%6,%7}, {%8,%9}, {%0,%1,%2,%3};" \
        : "+f"((c)[0]), "+f"((c)[1]), "+f"((c)[2]), "+f"((c)[3]) \
        : "r"((a)[0]), "r"((a)[1]), "r"((a)[2]), "r"((a)[3]), "r"((b)[0]), "r"((b)[1]))

// ----------------------------- conversions ---------------------------------
__global__ void __launch_bounds__(256) conv_split(const float* __restrict__ in,
                                                  bf16* __restrict__ hi, bf16* __restrict__ lo)
{
    size_t i = ((size_t)blockIdx.x * 256 + threadIdx.x) * 4;
    float4 v = *(const float4*)(in + i);
    bf16 h0 = __float2bfloat16(v.x), h1 = __float2bfloat16(v.y);
    bf16 h2 = __float2bfloat16(v.z), h3 = __float2bfloat16(v.w);
    hi[i+0] = h0; hi[i+1] = h1; hi[i+2] = h2; hi[i+3] = h3;
    lo[i+0] = __float2bfloat16(v.x - __bfloat162float(h0));
    lo[i+1] = __float2bfloat16(v.y - __bfloat162float(h1));
    lo[i+2] = __float2bfloat16(v.z - __bfloat162float(h2));
    lo[i+3] = __float2bfloat16(v.w - __bfloat162float(h3));
}

__global__ void __launch_bounds__(256) conv_wT(const float* __restrict__ w,
                                               bf16* __restrict__ hi, bf16* __restrict__ lo)
{
    const int m = blockIdx.z;
    const float* W = w + (size_t)m * MM;
    bf16* Hi = hi + (size_t)m * MM;
    bf16* Lo = lo + (size_t)m * MM;
    __shared__ float t[32][33];
    const int r0 = blockIdx.y * 32, c0 = blockIdx.x * 32;
    const int tr = threadIdx.x >> 5, tc = threadIdx.x & 31;
#pragma unroll
    for (int i = 0; i < 4; i++)
        t[tr + 8 * i][tc] = W[(size_t)(r0 + tr + 8 * i) * DN + c0 + tc];
    __syncthreads();
#pragma unroll
    for (int i = 0; i < 4; i++) {
        int rr = tr + 8 * i;
        float v = t[tc][rr];
        bf16 h = __float2bfloat16(v);
        size_t o = (size_t)(c0 + rr) * DN + r0 + tc;
        Hi[o] = h;
        Lo[o] = __float2bfloat16(v - __bfloat162float(h));
    }
}

// -------- 3-term hi/lo GEMM, 512 threads / 16 warps, 3-stage pipeline -------
// C[r][c] = scl * sum_k A[r][k] * B[c][k]   (both operands K-major)
// MODE 0: Gram   -> Cf (fp32) + Chi/Clo    [triangular grid + mirror]
// MODE 1: square -> Chi/Clo, scl=(1/tr)^2  [triangular grid + mirror]
// MODE 2: MLP1   -> Chi/Clo = gelu(C*is + b1)
// MODE 3: MLP2   -> Cf = C*is + b2
template <int MODE>
__global__ void __launch_bounds__(512, 1) gemm_k(
    const bf16* __restrict__ Ahi, const bf16* __restrict__ Alo, long lda, long aoffz,
    const bf16* __restrict__ Bhi, const bf16* __restrict__ Blo,
    float* __restrict__ Cf, bf16* __restrict__ Chi, bf16* __restrict__ Clo,
    long ldc, long coffz,
    const float* __restrict__ bias, const float* __restrict__ sc,
    const float* __restrict__ trin)
{
    extern __shared__ char smem[];
    const uint32_t sb = smem_u32(smem);

    const int tid = threadIdx.x;
    const int wid = tid >> 5, lane = tid & 31;
    const int wr = wid >> 2, wc = wid & 3;       // 4x4 warps, 32x32 warp tiles
    const int z = blockIdx.z;

    int row0, col0;
    if (MODE <= 1) {
        int t = blockIdx.x, ti = 0;
        while (t >= 8 - ti) { t -= 8 - ti; ti++; }
        row0 = ti * 128; col0 = (ti + t) * 128;
    } else {
        row0 = blockIdx.y * 128; col0 = blockIdx.x * 128;
    }

    const bf16* Ah = Ahi + (size_t)z * aoffz + (size_t)row0 * lda;
    const bf16* Al = Alo + (size_t)z * aoffz + (size_t)row0 * lda;
    const bf16* Bh = Bhi + (size_t)z * MM + (size_t)col0 * DN;
    const bf16* Bl = Blo + (size_t)z * MM + (size_t)col0 * DN;

    const bf16* gbase[4] = {Ah, Al, Bh, Bl};
    const long  gstr [4] = {lda, lda, DN, DN};

    // stage loader: 4 matrices x 128 rows x 64 bf16 (128B); 512 thr x 8 iters
    auto load_stage = [&](int st, int k0) {
        const uint32_t base = sb + (uint32_t)st * STG4;
        const int ch = tid & 7;
        const int rlo = tid >> 3;                 // 0..63
#pragma unroll
        for (int t = 0; t < 8; t++) {
            const int mat = t >> 1;
            const int r = ((t & 1) << 6) + rlo;   // 0..127
            cp16(base + (uint32_t)mat * MATB + (uint32_t)(r * RSEB + ch * 16),
                 gbase[mat] + (long)r * gstr[mat] + k0 + ch * 8);
        }
        CP_COMMIT();
    };

    float acc[2][4][4];
#pragma unroll
    for (int mi = 0; mi < 2; mi++)
#pragma unroll
        for (int ni = 0; ni < 4; ni++)
#pragma unroll
            for (int q = 0; q < 4; q++) acc[mi][ni][q] = 0.0f;

    load_stage(0, 0);
    load_stage(1, BK);

    const int arow = (lane & 7) + ((lane >> 3) & 1) * 8;
    const int acol = (lane >> 4) * 16;
    const int brow = (lane & 7) + ((lane >> 4) & 1) * 8;
    const int bcol = ((lane >> 3) & 1) * 16;

    for (int s = 0; s < NKS; s++) {
        if (s < NKS - 1) { CP_WAIT(1); } else { CP_WAIT(0); }
        __syncthreads();
        if (s + 2 < NKS) load_stage((s + 2) % 3, (s + 2) * BK);

        const uint32_t stb = sb + (uint32_t)(s % 3) * STG4;
        const uint32_t aBh = stb + (uint32_t)((wr * 32 + arow) * RSEB) + acol;
        const uint32_t aBl = aBh + MATB;
        const uint32_t bBh = stb + 2u * MATB + (uint32_t)((wc * 32 + brow) * RSEB) + bcol;
        const uint32_t bBl = bBh + MATB;

#pragma unroll
        for (int kk = 0; kk < 4; kk++) {
            const uint32_t ko = (uint32_t)(kk * 32);
            uint32_t ah[2][4], al[2][4], bh[4][2], bl[4][2];
#pragma unroll
            for (int mi = 0; mi < 2; mi++) {
                LDSM4(ah[mi][0], ah[mi][1], ah[mi][2], ah[mi][3], aBh + ko + (uint32_t)(mi * 16 * RSEB));
                LDSM4(al[mi][0], al[mi][1], al[mi][2], al[mi][3], aBl + ko + (uint32_t)(mi * 16 * RSEB));
            }
#pragma unroll
            for (int p = 0; p < 2; p++) {
                LDSM4(bh[2*p][0], bh[2*p][1], bh[2*p+1][0], bh[2*p+1][1], bBh + ko + (uint32_t)(p * 16 * RSEB));
                LDSM4(bl[2*p][0], bl[2*p][1], bl[2*p+1][0], bl[2*p+1][1], bBl + ko + (uint32_t)(p * 16 * RSEB));
            }
#pragma unroll
            for (int mi = 0; mi < 2; mi++)
#pragma unroll
                for (int ni = 0; ni < 4; ni++) MMA16816(acc[mi][ni], ah[mi], bh[ni]);
#pragma unroll
            for (int mi = 0; mi < 2; mi++)
#pragma unroll
                for (int ni = 0; ni < 4; ni++) MMA16816(acc[mi][ni], ah[mi], bl[ni]);
#pragma unroll
            for (int mi = 0; mi < 2; mi++)
#pragma unroll
                for (int ni = 0; ni < 4; ni++) MMA16816(acc[mi][ni], al[mi], bh[ni]);
        }
        __syncthreads();
    }

    // ------------------------------ epilogue -------------------------------
    float scl = 1.0f;
    if (MODE == 1) { float it = 1.0f / trin[z]; scl = it * it; }
    if (MODE >= 2) scl = sc[z];
    const int gID = lane >> 2, tg = lane & 3;
    const bool mirror = (MODE <= 1) && (row0 != col0);
    float* ts = (float*)smem;

#pragma unroll
    for (int mi = 0; mi < 2; mi++)
#pragma unroll
        for (int ni = 0; ni < 4; ni++)
#pragma unroll
            for (int hf = 0; hf < 2; hf++) {
                const int rl = wr * 32 + mi * 16 + gID + hf * 8;
                const int cl = wc * 32 + ni * 8 + tg * 2;
                float v0 = acc[mi][ni][hf * 2 + 0] * scl;
                float v1 = acc[mi][ni][hf * 2 + 1] * scl;
                if (MODE >= 2) {
                    v0 += bias[z * DN + col0 + cl];
                    v1 += bias[z * DN + col0 + cl + 1];
                }
                if (MODE == 2) {
                    v0 = 0.5f * v0 * (1.0f + erff(v0 * 0.70710678118654752f));
                    v1 = 0.5f * v1 * (1.0f + erff(v1 * 0.70710678118654752f));
                }
                const size_t off = (size_t)z * coffz + (size_t)(row0 + rl) * ldc + col0 + cl;
                if (MODE == 0 || MODE == 3) {
                    float2 f2; f2.x = v0; f2.y = v1;
                    *(float2*)(Cf + off) = f2;
                }
                if (MODE <= 2) {
                    bf16 h0 = __float2bfloat16(v0);
                    bf16 h1 = __float2bfloat16(v1);
                    __nv_bfloat162 hh; hh.x = h0; hh.y = h1;
                    __nv_bfloat162 ll;
                    ll.x = __float2bfloat16(v0 - __bfloat162float(h0));
                    ll.y = __float2bfloat16(v1 - __bfloat162float(h1));
                    *(__nv_bfloat162*)(Chi + off) = hh;
                    *(__nv_bfloat162*)(Clo + off) = ll;
                }
                if (mirror) {
                    ts[rl * 129 + cl] = v0;
                    ts[rl * 129 + cl + 1] = v1;
                }
            }

    if (mirror) {
        __syncthreads();
#pragma unroll 4
        for (int i = 0; i < 16; i++) {
            int lin = i * 1024 + tid * 2;
            int mr = lin >> 7, mc = lin & 127;
            float v0 = ts[mc * 129 + mr];
            float v1 = ts[(mc + 1) * 129 + mr];
            const size_t off = (size_t)z * coffz + (size_t)(col0 + mr) * ldc + row0 + mc;
            if (MODE == 0) {
                float2 f2; f2.x = v0; f2.y = v1;
                *(float2*)(Cf + off) = f2;
            }
            bf16 h0 = __float2bfloat16(v0);
            bf16 h1 = __float2bfloat16(v1);
            __nv_bfloat162 hh; hh.x = h0; hh.y = h1;
            __nv_bfloat162 ll;
            ll.x = __float2bfloat16(v0 - __bfloat162float(h0));
            ll.y = __float2bfloat16(v1 - __bfloat162float(h1));
            *(__nv_bfloat162*)(Chi + off) = hh;
            *(__nv_bfloat162*)(Clo + off) = ll;
        }
    }
}

// --------------------------- small kernels ----------------------------------
__global__ void __launch_bounds__(256) k_trace_f(const float* __restrict__ G,
                                                 float* __restrict__ out)
{
    const int m = blockIdx.x;
    float sum = 0.0f;
    for (int d = threadIdx.x; d < DN; d += 256)
        sum += G[(size_t)m * MM + (size_t)d * DN + d];
    __shared__ float red[256];
    red[threadIdx.x] = sum; __syncthreads();
    for (int off = 128; off > 0; off >>= 1) {
        if (threadIdx.x < off) red[threadIdx.x] += red[threadIdx.x + off];
        __syncthreads();
    }
    if (threadIdx.x == 0) out[m] = red[0];
}

__global__ void __launch_bounds__(256) k_trace_hl(const bf16* __restrict__ Ph,
                                                  const bf16* __restrict__ Pl,
                                                  float* __restrict__ out)
{
    const int m = blockIdx.x;
    float sum = 0.0f;
    for (int d = threadIdx.x; d < DN; d += 256) {
        size_t o = (size_t)m * MM + (size_t)d * DN + d;
        sum += __bfloat162float(Ph[o]) + __bfloat162float(Pl[o]);
    }
    __shared__ float red[256];
    red[threadIdx.x] = sum; __syncthreads();
    for (int off = 128; off > 0; off >>= 1) {
        if (threadIdx.x < off) red[threadIdx.x] += red[threadIdx.x + off];
        __syncthreads();
    }
    if (threadIdx.x == 0) out[m] = red[0];
}

__global__ void __launch_bounds__(256) k_rowsum(const bf16* __restrict__ Ph,
                                                const bf16* __restrict__ Pl,
                                                float* __restrict__ v)
{
    const int m = blockIdx.y, r = blockIdx.x;
    const size_t o = (size_t)m * MM + (size_t)r * DN;
    float sum = 0.0f;
    for (int c = threadIdx.x; c < DN; c += 256)
        sum += __bfloat162float(Ph[o + c]) + __bfloat162float(Pl[o + c]);
    __shared__ float red[256];
    red[threadIdx.x] = sum; __syncthreads();
    for (int off = 128; off > 0; off >>= 1) {
        if (threadIdx.x < off) red[threadIdx.x] += red[threadIdx.x + off];
        __syncthreads();
    }
    if (threadIdx.x == 0) v[m * DN + r] = red[0];
}

__global__ void __launch_bounds__(256) k_matvec(const float* __restrict__ G,
                                                const float* __restrict__ v,
                                                float* __restrict__ gv)
{
    const int m = blockIdx.y, r = blockIdx.x;
    const float* row = G + (size_t)m * MM + (size_t)r * DN;
    const float* vm = v + m * DN;
    float4 a = *(const float4*)&row[threadIdx.x * 4];
    float4 b = *(const float4*)&vm[threadIdx.x * 4];
    float sum = a.x * b.x + a.y * b.y + a.z * b.z + a.w * b.w;
    __shared__ float red[256];
    red[threadIdx.x] = sum; __syncthreads();
    for (int off = 128; off > 0; off >>= 1) {
        if (threadIdx.x < off) red[threadIdx.x] += red[threadIdx.x + off];
        __syncthreads();
    }
    if (threadIdx.x == 0) gv[m * DN + r] = red[0];
}

__global__ void __launch_bounds__(256) k_sigma(const float* __restrict__ v,
                                               const float* __restrict__ gv,
                                               float* __restrict__ is_)
{
    const int m = blockIdx.x;
    float num = 0.0f, den = 0.0f;
    for (int d = threadIdx.x; d < DN; d += 256) {
        float vv = v[m * DN + d];
        num += vv * gv[m * DN + d];
        den += vv * vv;
    }
    __shared__ float rn[256], rd[256];
    rn[threadIdx.x] = num; rd[threadIdx.x] = den; __syncthreads();
    for (int off = 128; off > 0; off >>= 1) {
        if (threadIdx.x < off) { rn[threadIdx.x] += rn[threadIdx.x + off]; rd[threadIdx.x] += rd[threadIdx.x + off]; }
        __syncthreads();
    }
    if (threadIdx.x == 0) is_[m] = sqrtf(rd[0] / rn[0]);
}

// ---------------------------------------------------------------------------
extern "C" void kernel_launch(void* const* d_in, const int* in_sizes, int n_in,
                              void* d_out, int out_size)
{
    const float* x  = (const float*)d_in[0];
    const float* w1 = (const float*)d_in[1];
    const float* b1 = (const float*)d_in[2];
    const float* w2 = (const float*)d_in[3];
    const float* b2 = (const float*)d_in[4];
    float* out = (float*)d_out;

    bf16 *xhi, *xlo, *wth, *wtl, *P0h, *P0l, *P1h, *P1l, *hhi, *hlo;
    float *G, *tr, *v, *gv, *is_;
    cudaGetSymbolAddress((void**)&xhi, g_xhi); cudaGetSymbolAddress((void**)&xlo, g_xlo);
    cudaGetSymbolAddress((void**)&wth, g_wth); cudaGetSymbolAddress((void**)&wtl, g_wtl);
    cudaGetSymbolAddress((void**)&G, g_G);
    cudaGetSymbolAddress((void**)&P0h, g_P0h); cudaGetSymbolAddress((void**)&P0l, g_P0l);
    cudaGetSymbolAddress((void**)&P1h, g_P1h); cudaGetSymbolAddress((void**)&P1l, g_P1l);
    cudaGetSymbolAddress((void**)&hhi, g_hhi); cudaGetSymbolAddress((void**)&hlo, g_hlo);
    cudaGetSymbolAddress((void**)&tr, g_tr);   cudaGetSymbolAddress((void**)&v, g_v);
    cudaGetSymbolAddress((void**)&gv, g_gv);   cudaGetSymbolAddress((void**)&is_, g_is);

    cudaFuncSetAttribute(gemm_k<0>, cudaFuncAttributeMaxDynamicSharedMemorySize, SMEM_BYTES);
    cudaFuncSetAttribute(gemm_k<1>, cudaFuncAttributeMaxDynamicSharedMemorySize, SMEM_BYTES);
    cudaFuncSetAttribute(gemm_k<2>, cudaFuncAttributeMaxDynamicSharedMemorySize, SMEM_BYTES);
    cudaFuncSetAttribute(gemm_k<3>, cudaFuncAttributeMaxDynamicSharedMemorySize, SMEM_BYTES);

    conv_split<<<(unsigned)((size_t)BATCH * RS / 4 / 256), 256>>>(x, xhi, xlo);
    conv_wT<<<dim3(32, 32, NB), 256>>>(w1, wth, wtl);
    conv_wT<<<dim3(32, 32, NB), 256>>>(w2, wth + (size_t)NB * MM, wtl + (size_t)NB * MM);

    // Gram: G (fp32) + P0 hi/lo, triangular grid; trace from fp32 G
    gemm_k<0><<<dim3(36, 1, NMAT), 512, SMEM_BYTES>>>(
        wth, wtl, DN, (long)MM, wth, wtl, G, P0h, P0l, DN, (long)MM,
        nullptr, nullptr, nullptr);
    k_trace_f<<<NMAT, 256>>>(G, tr);

    // hi/lo trace-normalized squarings (triangular + mirror) — ALL hi/lo
    bf16 *pih = P0h, *pil = P0l, *poh = P1h, *pol = P1l;
    for (int s = 0; s < NSQ; s++) {
        gemm_k<1><<<dim3(36, 1, NMAT), 512, SMEM_BYTES>>>(
            pih, pil, DN, (long)MM, pih, pil, nullptr, poh, pol, DN, (long)MM,
            nullptr, nullptr, tr + s * NMAT);
        k_trace_hl<<<NMAT, 256>>>(poh, pol, tr + (s + 1) * NMAT);
        bf16* t1 = pih; pih = poh; poh = t1;
        bf16* t2 = pil; pil = pol; pol = t2;
    }

    // Rayleigh quotient on fp32 G with v = P_final @ 1
    k_rowsum<<<dim3(DN, NMAT), 256>>>(pih, pil, v);
    k_matvec<<<dim3(DN, NMAT), 256>>>(G, v, gv);
    k_sigma<<<NMAT, 256>>>(v, gv, is_);

    // MLP
    gemm_k<2><<<dim3(8, 32, NB), 512, SMEM_BYTES>>>(
        xhi, xlo, RS, (long)DN, wth, wtl, nullptr, hhi, hlo, RS, (long)DN,
        b1, is_, nullptr);
    gemm_k<3><<<dim3(8, 32, NB), 512, SMEM_BYTES>>>(
        hhi, hlo, RS, (long)DN, wth + (size_t)NB * MM, wtl + (size_t)NB * MM,
        out, nullptr, nullptr, RS, (long)DN, b2, is_ + NB, nullptr);
}

// round 11
// speedup vs baseline: 1.1347x; 1.1291x over previous
#include <cuda_runtime.h>
#include <cuda_bf16.h>
#include <cstdint>
#include <math.h>

#define NB 25
#define BATCH 4096
#define DN 1024
#define RS (NB * DN)
#define NMAT (2 * NB)
#define MM ((size_t)DN * DN)
#define NSQ_HL 7                 // hi/lo squarings (small-gap regime: precision required)
#define NSQ_BF 3                 // bf16 single-term tail (gap ~1: noise not amplified)
#define NSQ (NSQ_HL + NSQ_BF)
#define BK 64
#define NKS (DN / BK)            // 16 k-stages
#define RSEB 144                 // smem row stride bytes (128B data + 16B pad)
#define MATB (128 * RSEB)        // 18432 B per matrix tile
#define STG4 (4 * MATB)          // 73728 B per stage (4 mats)
#define SMEM_BYTES (3 * STG4)    // 221184, 3-stage pipeline
#define STG2 (2 * MATB)          // 36864 B per stage (2 mats)
#define SMEM1 (2 * STG2)         // 73728 (1-term kernel, 2 stages)

typedef __nv_bfloat16 bf16;

// ----------------------------- scratch -------------------------------------
__device__ bf16  g_xhi[(size_t)BATCH * RS];
__device__ bf16  g_xlo[(size_t)BATCH * RS];
__device__ bf16  g_wth[NMAT * MM];
__device__ bf16  g_wtl[NMAT * MM];
__device__ float g_G  [NMAT * MM];
__device__ bf16  g_P0h[NMAT * MM];
__device__ bf16  g_P0l[NMAT * MM];
__device__ bf16  g_P1h[NMAT * MM];
__device__ bf16  g_P1l[NMAT * MM];
__device__ bf16  g_hhi[(size_t)BATCH * RS];
__device__ bf16  g_hlo[(size_t)BATCH * RS];
__device__ float g_tr [(NSQ + 1) * NMAT];
__device__ float g_v  [NMAT * DN];
__device__ float g_gv [NMAT * DN];
__device__ float g_is [NMAT];

// ----------------------------- PTX helpers ---------------------------------
__device__ __forceinline__ uint32_t smem_u32(const void* p) {
    uint32_t a;
    asm("{ .reg .u64 t; cvta.to.shared.u64 t, %1; cvt.u32.u64 %0, t; }" : "=r"(a) : "l"(p));
    return a;
}
__device__ __forceinline__ void cp16(uint32_t s, const void* g) {
    asm volatile("cp.async.cg.shared.global [%0], [%1], 16;" :: "r"(s), "l"(g));
}
#define CP_COMMIT() asm volatile("cp.async.commit_group;" ::: "memory")
#define CP_WAIT(N)  asm volatile("cp.async.wait_group %0;" :: "n"(N) : "memory")

#define LDSM4(r0, r1, r2, r3, addr) \
    asm volatile("ldmatrix.sync.aligned.m8n8.x4.shared.b16 {%0,%1,%2,%3}, [%4];" \
        : "=r"(r0), "=r"(r1), "=r"(r2), "=r"(r3) : "r"(addr))

#define MMA16816(c, a, b) \
    asm volatile("mma.sync.aligned.m16n8k16.row.col.f32.bf16.bf16.f32 " \
        "{%0,%1,%2,%3}, {%4,%5,%6,%7}, {%8,%9}, {%0,%1,%2,%3};" \
        : "+f"((c)[0]), "+f"((c)[1]), "+f"((c)[2]), "+f"((c)[3]) \
        : "r"((a)[0]), "r"((a)[1]), "r"((a)[2]), "r"((a)[3]), "r"((b)[0]), "r"((b)[1]))

// ----------------------------- conversions ---------------------------------
__global__ void __launch_bounds__(256) conv_split(const float* __restrict__ in,
                                                  bf16* __restrict__ hi, bf16* __restrict__ lo)
{
    size_t i = ((size_t)blockIdx.x * 256 + threadIdx.x) * 4;
    float4 v = *(const float4*)(in + i);
    bf16 h0 = __float2bfloat16(v.x), h1 = __float2bfloat16(v.y);
    bf16 h2 = __float2bfloat16(v.z), h3 = __float2bfloat16(v.w);
    hi[i+0] = h0; hi[i+1] = h1; hi[i+2] = h2; hi[i+3] = h3;
    lo[i+0] = __float2bfloat16(v.x - __bfloat162float(h0));
    lo[i+1] = __float2bfloat16(v.y - __bfloat162float(h1));
    lo[i+2] = __float2bfloat16(v.z - __bfloat162float(h2));
    lo[i+3] = __float2bfloat16(v.w - __bfloat162float(h3));
}

__global__ void __launch_bounds__(256) conv_wT(const float* __restrict__ w,
                                               bf16* __restrict__ hi, bf16* __restrict__ lo)
{
    const int m = blockIdx.z;
    const float* W = w + (size_t)m * MM;
    bf16* Hi = hi + (size_t)m * MM;
    bf16* Lo = lo + (size_t)m * MM;
    __shared__ float t[32][33];
    const int r0 = blockIdx.y * 32, c0 = blockIdx.x * 32;
    const int tr = threadIdx.x >> 5, tc = threadIdx.x & 31;
#pragma unroll
    for (int i = 0; i < 4; i++)
        t[tr + 8 * i][tc] = W[(size_t)(r0 + tr + 8 * i) * DN + c0 + tc];
    __syncthreads();
#pragma unroll
    for (int i = 0; i < 4; i++) {
        int rr = tr + 8 * i;
        float v = t[tc][rr];
        bf16 h = __float2bfloat16(v);
        size_t o = (size_t)(c0 + rr) * DN + r0 + tc;
        Hi[o] = h;
        Lo[o] = __float2bfloat16(v - __bfloat162float(h));
    }
}

// -------- 3-term hi/lo GEMM, 512 threads / 16 warps, 3-stage pipeline -------
// MODE 0: Gram   -> Cf (fp32) + Chi/Clo    [triangular grid + mirror]
// MODE 1: square -> Chi/Clo, scl=(1/tr)^2  [triangular grid + mirror]
// MODE 2: MLP1   -> Chi/Clo = gelu(C*is + b1)
// MODE 3: MLP2   -> Cf = C*is + b2
template <int MODE>
__global__ void __launch_bounds__(512, 1) gemm_k(
    const bf16* __restrict__ Ahi, const bf16* __restrict__ Alo, long lda, long aoffz,
    const bf16* __restrict__ Bhi, const bf16* __restrict__ Blo,
    float* __restrict__ Cf, bf16* __restrict__ Chi, bf16* __restrict__ Clo,
    long ldc, long coffz,
    const float* __restrict__ bias, const float* __restrict__ sc,
    const float* __restrict__ trin)
{
    extern __shared__ char smem[];
    const uint32_t sb = smem_u32(smem);

    const int tid = threadIdx.x;
    const int wid = tid >> 5, lane = tid & 31;
    const int wr = wid >> 2, wc = wid & 3;       // 4x4 warps, 32x32 warp tiles
    const int z = blockIdx.z;

    int row0, col0;
    if (MODE <= 1) {
        int t = blockIdx.x, ti = 0;
        while (t >= 8 - ti) { t -= 8 - ti; ti++; }
        row0 = ti * 128; col0 = (ti + t) * 128;
    } else {
        row0 = blockIdx.y * 128; col0 = blockIdx.x * 128;
    }

    const bf16* Ah = Ahi + (size_t)z * aoffz + (size_t)row0 * lda;
    const bf16* Al = Alo + (size_t)z * aoffz + (size_t)row0 * lda;
    const bf16* Bh = Bhi + (size_t)z * MM + (size_t)col0 * DN;
    const bf16* Bl = Blo + (size_t)z * MM + (size_t)col0 * DN;

    const bf16* gbase[4] = {Ah, Al, Bh, Bl};
    const long  gstr [4] = {lda, lda, DN, DN};

    auto load_stage = [&](int st, int k0) {
        const uint32_t base = sb + (uint32_t)st * STG4;
        const int ch = tid & 7;
        const int rlo = tid >> 3;                 // 0..63
#pragma unroll
        for (int t = 0; t < 8; t++) {
            const int mat = t >> 1;
            const int r = ((t & 1) << 6) + rlo;   // 0..127
            cp16(base + (uint32_t)mat * MATB + (uint32_t)(r * RSEB + ch * 16),
                 gbase[mat] + (long)r * gstr[mat] + k0 + ch * 8);
        }
        CP_COMMIT();
    };

    float acc[2][4][4];
#pragma unroll
    for (int mi = 0; mi < 2; mi++)
#pragma unroll
        for (int ni = 0; ni < 4; ni++)
#pragma unroll
            for (int q = 0; q < 4; q++) acc[mi][ni][q] = 0.0f;

    load_stage(0, 0);
    load_stage(1, BK);

    const int arow = (lane & 7) + ((lane >> 3) & 1) * 8;
    const int acol = (lane >> 4) * 16;
    const int brow = (lane & 7) + ((lane >> 4) & 1) * 8;
    const int bcol = ((lane >> 3) & 1) * 16;

    for (int s = 0; s < NKS; s++) {
        if (s < NKS - 1) { CP_WAIT(1); } else { CP_WAIT(0); }
        __syncthreads();
        if (s + 2 < NKS) load_stage((s + 2) % 3, (s + 2) * BK);

        const uint32_t stb = sb + (uint32_t)(s % 3) * STG4;
        const uint32_t aBh = stb + (uint32_t)((wr * 32 + arow) * RSEB) + acol;
        const uint32_t aBl = aBh + MATB;
        const uint32_t bBh = stb + 2u * MATB + (uint32_t)((wc * 32 + brow) * RSEB) + bcol;
        const uint32_t bBl = bBh + MATB;

#pragma unroll
        for (int kk = 0; kk < 4; kk++) {
            const uint32_t ko = (uint32_t)(kk * 32);
            uint32_t ah[2][4], al[2][4], bh[4][2], bl[4][2];
#pragma unroll
            for (int mi = 0; mi < 2; mi++) {
                LDSM4(ah[mi][0], ah[mi][1], ah[mi][2], ah[mi][3], aBh + ko + (uint32_t)(mi * 16 * RSEB));
                LDSM4(al[mi][0], al[mi][1], al[mi][2], al[mi][3], aBl + ko + (uint32_t)(mi * 16 * RSEB));
            }
#pragma unroll
            for (int p = 0; p < 2; p++) {
                LDSM4(bh[2*p][0], bh[2*p][1], bh[2*p+1][0], bh[2*p+1][1], bBh + ko + (uint32_t)(p * 16 * RSEB));
                LDSM4(bl[2*p][0], bl[2*p][1], bl[2*p+1][0], bl[2*p+1][1], bBl + ko + (uint32_t)(p * 16 * RSEB));
            }
#pragma unroll
            for (int mi = 0; mi < 2; mi++)
#pragma unroll
                for (int ni = 0; ni < 4; ni++) MMA16816(acc[mi][ni], ah[mi], bh[ni]);
#pragma unroll
            for (int mi = 0; mi < 2; mi++)
#pragma unroll
                for (int ni = 0; ni < 4; ni++) MMA16816(acc[mi][ni], ah[mi], bl[ni]);
#pragma unroll
            for (int mi = 0; mi < 2; mi++)
#pragma unroll
                for (int ni = 0; ni < 4; ni++) MMA16816(acc[mi][ni], al[mi], bh[ni]);
        }
        __syncthreads();
    }

    // ------------------------------ epilogue -------------------------------
    float scl = 1.0f;
    if (MODE == 1) { float it = 1.0f / trin[z]; scl = it * it; }
    if (MODE >= 2) scl = sc[z];
    const int gID = lane >> 2, tg = lane & 3;
    const bool mirror = (MODE <= 1) && (row0 != col0);
    float* ts = (float*)smem;

#pragma unroll
    for (int mi = 0; mi < 2; mi++)
#pragma unroll
        for (int ni = 0; ni < 4; ni++)
#pragma unroll
            for (int hf = 0; hf < 2; hf++) {
                const int rl = wr * 32 + mi * 16 + gID + hf * 8;
                const int cl = wc * 32 + ni * 8 + tg * 2;
                float v0 = acc[mi][ni][hf * 2 + 0] * scl;
                float v1 = acc[mi][ni][hf * 2 + 1] * scl;
                if (MODE >= 2) {
                    v0 += bias[z * DN + col0 + cl];
                    v1 += bias[z * DN + col0 + cl + 1];
                }
                if (MODE == 2) {
                    v0 = 0.5f * v0 * (1.0f + erff(v0 * 0.70710678118654752f));
                    v1 = 0.5f * v1 * (1.0f + erff(v1 * 0.70710678118654752f));
                }
                const size_t off = (size_t)z * coffz + (size_t)(row0 + rl) * ldc + col0 + cl;
                if (MODE == 0 || MODE == 3) {
                    float2 f2; f2.x = v0; f2.y = v1;
                    *(float2*)(Cf + off) = f2;
                }
                if (MODE <= 2) {
                    bf16 h0 = __float2bfloat16(v0);
                    bf16 h1 = __float2bfloat16(v1);
                    __nv_bfloat162 hh; hh.x = h0; hh.y = h1;
                    __nv_bfloat162 ll;
                    ll.x = __float2bfloat16(v0 - __bfloat162float(h0));
                    ll.y = __float2bfloat16(v1 - __bfloat162float(h1));
                    *(__nv_bfloat162*)(Chi + off) = hh;
                    *(__nv_bfloat162*)(Clo + off) = ll;
                }
                if (mirror) {
                    ts[rl * 129 + cl] = v0;
                    ts[rl * 129 + cl + 1] = v1;
                }
            }

    if (mirror) {
        __syncthreads();
#pragma unroll 4
        for (int i = 0; i < 16; i++) {
            int lin = i * 1024 + tid * 2;
            int mr = lin >> 7, mc = lin & 127;
            float v0 = ts[mc * 129 + mr];
            float v1 = ts[(mc + 1) * 129 + mr];
            const size_t off = (size_t)z * coffz + (size_t)(col0 + mr) * ldc + row0 + mc;
            if (MODE == 0) {
                float2 f2; f2.x = v0; f2.y = v1;
                *(float2*)(Cf + off) = f2;
            }
            bf16 h0 = __float2bfloat16(v0);
            bf16 h1 = __float2bfloat16(v1);
            __nv_bfloat162 hh; hh.x = h0; hh.y = h1;
            __nv_bfloat162 ll;
            ll.x = __float2bfloat16(v0 - __bfloat162float(h0));
            ll.y = __float2bfloat16(v1 - __bfloat162float(h1));
            *(__nv_bfloat162*)(Chi + off) = hh;
            *(__nv_bfloat162*)(Clo + off) = ll;
        }
    }
}

// ------------- 1-term bf16 squaring GEMM, 2-stage, 2 CTAs/SM ----------------
// Only for the LAST squarings (gap ~1: bf16 noise is not amplified).
__global__ void __launch_bounds__(256, 2) gemm1_k(
    const bf16* __restrict__ Ph, bf16* __restrict__ Po,
    const float* __restrict__ trin)
{
    extern __shared__ char smem[];
    const uint32_t sb = smem_u32(smem);

    const int tid = threadIdx.x;
    const int wid = tid >> 5, lane = tid & 31;
    const int wr = wid >> 1, wc = wid & 1;
    const int z = blockIdx.z;

    int t = blockIdx.x, ti = 0;
    while (t >= 8 - ti) { t -= 8 - ti; ti++; }
    const int row0 = ti * 128, col0 = (ti + t) * 128;

    const bf16* Ah = Ph + (size_t)z * MM + (size_t)row0 * DN;
    const bf16* Bh = Ph + (size_t)z * MM + (size_t)col0 * DN;

    auto load_stage = [&](int st, int k0) {
        const uint32_t base = sb + (uint32_t)st * STG2;
        const int ch = tid & 7;
        const int rlo = tid >> 3;
#pragma unroll
        for (int t2 = 0; t2 < 8; t2++) {
            const int mat = t2 >> 2;
            const int r = ((t2 & 3) << 5) + rlo;
            const bf16* src = mat ? Bh : Ah;
            cp16(base + (uint32_t)mat * MATB + (uint32_t)(r * RSEB + ch * 16),
                 src + (long)r * DN + k0 + ch * 8);
        }
        CP_COMMIT();
    };

    float acc[2][8][4];
#pragma unroll
    for (int mi = 0; mi < 2; mi++)
#pragma unroll
        for (int ni = 0; ni < 8; ni++)
#pragma unroll
            for (int q = 0; q < 4; q++) acc[mi][ni][q] = 0.0f;

    load_stage(0, 0);

    const int arow = (lane & 7) + ((lane >> 3) & 1) * 8;
    const int acol = (lane >> 4) * 16;
    const int brow = (lane & 7) + ((lane >> 4) & 1) * 8;
    const int bcol = ((lane >> 3) & 1) * 16;

    for (int s = 0; s < NKS; s++) {
        CP_WAIT(0);
        __syncthreads();
        if (s + 1 < NKS) load_stage((s + 1) & 1, (s + 1) * BK);

        const uint32_t stb = sb + (uint32_t)(s & 1) * STG2;
        const uint32_t aB = stb + (uint32_t)((wr * 32 + arow) * RSEB) + acol;
        const uint32_t bB = stb + MATB + (uint32_t)((wc * 64 + brow) * RSEB) + bcol;

#pragma unroll
        for (int kk = 0; kk < 4; kk++) {
            const uint32_t ko = (uint32_t)(kk * 32);
            uint32_t ah[2][4], bh[8][2];
#pragma unroll
            for (int mi = 0; mi < 2; mi++)
                LDSM4(ah[mi][0], ah[mi][1], ah[mi][2], ah[mi][3], aB + ko + (uint32_t)(mi * 16 * RSEB));
#pragma unroll
            for (int p = 0; p < 4; p++)
                LDSM4(bh[2*p][0], bh[2*p][1], bh[2*p+1][0], bh[2*p+1][1], bB + ko + (uint32_t)(p * 16 * RSEB));
#pragma unroll
            for (int mi = 0; mi < 2; mi++)
#pragma unroll
                for (int ni = 0; ni < 8; ni++) MMA16816(acc[mi][ni], ah[mi], bh[ni]);
        }
        __syncthreads();
    }

    const float it = 1.0f / trin[z];
    const float scl = it * it;
    const int gID = lane >> 2, tg = lane & 3;
    const bool mirror = (row0 != col0);
    float* ts = (float*)smem;

#pragma unroll
    for (int mi = 0; mi < 2; mi++)
#pragma unroll
        for (int ni = 0; ni < 8; ni++)
#pragma unroll
            for (int hf = 0; hf < 2; hf++) {
                const int rl = wr * 32 + mi * 16 + gID + hf * 8;
                const int cl = wc * 64 + ni * 8 + tg * 2;
                float v0 = acc[mi][ni][hf * 2 + 0] * scl;
                float v1 = acc[mi][ni][hf * 2 + 1] * scl;
                const size_t off = (size_t)z * MM + (size_t)(row0 + rl) * DN + col0 + cl;
                __nv_bfloat162 hh;
                hh.x = __float2bfloat16(v0);
                hh.y = __float2bfloat16(v1);
                *(__nv_bfloat162*)(Po + off) = hh;
                if (mirror) {
                    ts[rl * 129 + cl] = v0;
                    ts[rl * 129 + cl + 1] = v1;
                }
            }

    if (mirror) {
        __syncthreads();
#pragma unroll 4
        for (int i = 0; i < 32; i++) {
            int lin = i * 512 + tid * 2;
            int mr = lin >> 7, mc = lin & 127;
            float v0 = ts[mc * 129 + mr];
            float v1 = ts[(mc + 1) * 129 + mr];
            const size_t off = (size_t)z * MM + (size_t)(col0 + mr) * DN + row0 + mc;
            __nv_bfloat162 hh;
            hh.x = __float2bfloat16(v0);
            hh.y = __float2bfloat16(v1);
            *(__nv_bfloat162*)(Po + off) = hh;
        }
    }
}

// --------------------------- small kernels ----------------------------------
__global__ void __launch_bounds__(256) k_trace_f(const float* __restrict__ G,
                                                 float* __restrict__ out)
{
    const int m = blockIdx.x;
    float sum = 0.0f;
    for (int d = threadIdx.x; d < DN; d += 256)
        sum += G[(size_t)m * MM + (size_t)d * DN + d];
    __shared__ float red[256];
    red[threadIdx.x] = sum; __syncthreads();
    for (int off = 128; off > 0; off >>= 1) {
        if (threadIdx.x < off) red[threadIdx.x] += red[threadIdx.x + off];
        __syncthreads();
    }
    if (threadIdx.x == 0) out[m] = red[0];
}

__global__ void __launch_bounds__(256) k_trace_hl(const bf16* __restrict__ Ph,
                                                  const bf16* __restrict__ Pl,
                                                  float* __restrict__ out)
{
    const int m = blockIdx.x;
    float sum = 0.0f;
    for (int d = threadIdx.x; d < DN; d += 256) {
        size_t o = (size_t)m * MM + (size_t)d * DN + d;
        sum += __bfloat162float(Ph[o]);
        if (Pl) sum += __bfloat162float(Pl[o]);
    }
    __shared__ float red[256];
    red[threadIdx.x] = sum; __syncthreads();
    for (int off = 128; off > 0; off >>= 1) {
        if (threadIdx.x < off) red[threadIdx.x] += red[threadIdx.x + off];
        __syncthreads();
    }
    if (threadIdx.x == 0) out[m] = red[0];
}

// Robust extractor: j = argmax_d |P[d][d]| (diag ~ lambda*v_d^2), then v = P[:,j].
// Avoids the ones-vector projection whose signal can cancel (R9 failure mode).
__global__ void __launch_bounds__(256) k_pickcol(const bf16* __restrict__ Ph,
                                                 float* __restrict__ v)
{
    const int m = blockIdx.x;
    const size_t base = (size_t)m * MM;
    __shared__ float bv[256];
    __shared__ int bi[256];
    float best = -1.0f; int bidx = 0;
    for (int d = threadIdx.x; d < DN; d += 256) {
        float val = fabsf(__bfloat162float(Ph[base + (size_t)d * DN + d]));
        if (val > best) { best = val; bidx = d; }
    }
    bv[threadIdx.x] = best; bi[threadIdx.x] = bidx;
    __syncthreads();
    for (int off = 128; off > 0; off >>= 1) {
        if (threadIdx.x < off && bv[threadIdx.x + off] > bv[threadIdx.x]) {
            bv[threadIdx.x] = bv[threadIdx.x + off];
            bi[threadIdx.x] = bi[threadIdx.x + off];
        }
        __syncthreads();
    }
    const int j = bi[0];
    // v = row j of P (P symmetric => column j), coalesced read
    for (int i = threadIdx.x; i < DN; i += 256)
        v[m * DN + i] = __bfloat162float(Ph[base + (size_t)j * DN + i]);
}

__global__ void __launch_bounds__(256) k_matvec(const float* __restrict__ G,
                                                const float* __restrict__ v,
                                                float* __restrict__ gv)
{
    const int m = blockIdx.y, r = blockIdx.x;
    const float* row = G + (size_t)m * MM + (size_t)r * DN;
    const float* vm = v + m * DN;
    float4 a = *(const float4*)&row[threadIdx.x * 4];
    float4 b = *(const float4*)&vm[threadIdx.x * 4];
    float sum = a.x * b.x + a.y * b.y + a.z * b.z + a.w * b.w;
    __shared__ float red[256];
    red[threadIdx.x] = sum; __syncthreads();
    for (int off = 128; off > 0; off >>= 1) {
        if (threadIdx.x < off) red[threadIdx.x] += red[threadIdx.x + off];
        __syncthreads();
    }
    if (threadIdx.x == 0) gv[m * DN + r] = red[0];
}

__global__ void __launch_bounds__(256) k_sigma(const float* __restrict__ v,
                                               const float* __restrict__ gv,
                                               float* __restrict__ is_)
{
    const int m = blockIdx.x;
    float num = 0.0f, den = 0.0f;
    for (int d = threadIdx.x; d < DN; d += 256) {
        float vv = v[m * DN + d];
        num += vv * gv[m * DN + d];
        den += vv * vv;
    }
    __shared__ float rn[256], rd[256];
    rn[threadIdx.x] = num; rd[threadIdx.x] = den; __syncthreads();
    for (int off = 128; off > 0; off >>= 1) {
        if (threadIdx.x < off) { rn[threadIdx.x] += rn[threadIdx.x + off]; rd[threadIdx.x] += rd[threadIdx.x + off]; }
        __syncthreads();
    }
    if (threadIdx.x == 0) is_[m] = sqrtf(rd[0] / rn[0]);
}

// ---------------------------------------------------------------------------
extern "C" void kernel_launch(void* const* d_in, const int* in_sizes, int n_in,
                              void* d_out, int out_size)
{
    const float* x  = (const float*)d_in[0];
    const float* w1 = (const float*)d_in[1];
    const float* b1 = (const float*)d_in[2];
    const float* w2 = (const float*)d_in[3];
    const float* b2 = (const float*)d_in[4];
    float* out = (float*)d_out;

    bf16 *xhi, *xlo, *wth, *wtl, *P0h, *P0l, *P1h, *P1l, *hhi, *hlo;
    float *G, *tr, *v, *gv, *is_;
    cudaGetSymbolAddress((void**)&xhi, g_xhi); cudaGetSymbolAddress((void**)&xlo, g_xlo);
    cudaGetSymbolAddress((void**)&wth, g_wth); cudaGetSymbolAddress((void**)&wtl, g_wtl);
    cudaGetSymbolAddress((void**)&G, g_G);
    cudaGetSymbolAddress((void**)&P0h, g_P0h); cudaGetSymbolAddress((void**)&P0l, g_P0l);
    cudaGetSymbolAddress((void**)&P1h, g_P1h); cudaGetSymbolAddress((void**)&P1l, g_P1l);
    cudaGetSymbolAddress((void**)&hhi, g_hhi); cudaGetSymbolAddress((void**)&hlo, g_hlo);
    cudaGetSymbolAddress((void**)&tr, g_tr);   cudaGetSymbolAddress((void**)&v, g_v);
    cudaGetSymbolAddress((void**)&gv, g_gv);   cudaGetSymbolAddress((void**)&is_, g_is);

    cudaFuncSetAttribute(gemm_k<0>, cudaFuncAttributeMaxDynamicSharedMemorySize, SMEM_BYTES);
    cudaFuncSetAttribute(gemm_k<1>, cudaFuncAttributeMaxDynamicSharedMemorySize, SMEM_BYTES);
    cudaFuncSetAttribute(gemm_k<2>, cudaFuncAttributeMaxDynamicSharedMemorySize, SMEM_BYTES);
    cudaFuncSetAttribute(gemm_k<3>, cudaFuncAttributeMaxDynamicSharedMemorySize, SMEM_BYTES);
    cudaFuncSetAttribute(gemm1_k,   cudaFuncAttributeMaxDynamicSharedMemorySize, SMEM1);

    conv_split<<<(unsigned)((size_t)BATCH * RS / 4 / 256), 256>>>(x, xhi, xlo);
    conv_wT<<<dim3(32, 32, NB), 256>>>(w1, wth, wtl);
    conv_wT<<<dim3(32, 32, NB), 256>>>(w2, wth + (size_t)NB * MM, wtl + (size_t)NB * MM);

    // Gram: G (fp32) + P0 hi/lo, triangular grid; trace from fp32 G
    gemm_k<0><<<dim3(36, 1, NMAT), 512, SMEM_BYTES>>>(
        wth, wtl, DN, (long)MM, wth, wtl, G, P0h, P0l, DN, (long)MM,
        nullptr, nullptr, nullptr);
    k_trace_f<<<NMAT, 256>>>(G, tr);

    // 7 hi/lo trace-normalized squarings (small-gap regime)
    bf16 *pih = P0h, *pil = P0l, *poh = P1h, *pol = P1l;
    int step = 0;
    for (int s = 0; s < NSQ_HL; s++, step++) {
        gemm_k<1><<<dim3(36, 1, NMAT), 512, SMEM_BYTES>>>(
            pih, pil, DN, (long)MM, pih, pil, nullptr, poh, pol, DN, (long)MM,
            nullptr, nullptr, tr + step * NMAT);
        k_trace_hl<<<NMAT, 256>>>(poh, pol, tr + (step + 1) * NMAT);
        bf16* t1 = pih; pih = poh; poh = t1;
        bf16* t2 = pil; pil = pol; pol = t2;
    }
    // 3 bf16 single-term tail squarings (gap ~1; robust extractor below)
    for (int s = 0; s < NSQ_BF; s++, step++) {
        gemm1_k<<<dim3(36, 1, NMAT), 256, SMEM1>>>(pih, poh, tr + step * NMAT);
        k_trace_hl<<<NMAT, 256>>>(poh, nullptr, tr + (step + 1) * NMAT);
        bf16* t1 = pih; pih = poh; poh = t1;
    }

    // Rayleigh quotient on fp32 G with v = argmax-diag column of P_final
    k_pickcol<<<NMAT, 256>>>(pih, v);
    k_matvec<<<dim3(DN, NMAT), 256>>>(G, v, gv);
    k_sigma<<<NMAT, 256>>>(v, gv, is_);

    // MLP
    gemm_k<2><<<dim3(8, 32, NB), 512, SMEM_BYTES>>>(
        xhi, xlo, RS, (long)DN, wth, wtl, nullptr, hhi, hlo, RS, (long)DN,
        b1, is_, nullptr);
    gemm_k<3><<<dim3(8, 32, NB), 512, SMEM_BYTES>>>(
        hhi, hlo, RS, (long)DN, wth + (size_t)NB * MM, wtl + (size_t)NB * MM,
        out, nullptr, nullptr, RS, (long)DN, b2, is_ + NB, nullptr);
}